// round 8
// baseline (speedup 1.0000x reference)
#include <cuda_runtime.h>

// Maxwell RNN: per-row linear recurrence. One block = one full row
// (8192 = 256 threads x 32 elems). No inter-block dependency.
//
//   gamma_t = (1 - 0.5*dt_t)*gamma_{t-1} + 0.5*dt_t*eps_t,  gamma_{-1} = 0
//   sig_t   = 2.5*eps_t - gamma_{t-1}
//
// sig is affine in the thread-start state g: sig_j = C_j - Pp_j * g with
// C_j = 2.5*e_j - Qp_j. C/Pp overwrite ee/dd in place (fixup = independent
// FMAs, no serial replay). EPT=32 doubles per-thread MLP (16 batched
// LDG.128) — R6/R7 showed MLP, not occupancy, is the governing resource.
// Streaming hints (__ldcs/__stcs): data is strictly single-touch.

constexpr int Bn  = 4096;
constexpr int Tn  = 8192;
constexpr int TPB = 256;
constexpr int EPT = 32;
constexpr int NV  = EPT / 4;            // 8 float4 per array
constexpr int NW  = TPB / 32;           // 8 warps
static_assert(TPB * EPT == Tn, "one block = one row");

__global__ void __launch_bounds__(TPB)
maxwell_row_kernel(const float* __restrict__ eps, const float* __restrict__ dt,
                   float* __restrict__ out) {
    __shared__ float sWP[NW];
    __shared__ float sWQ[NW];

    const int tid  = threadIdx.x;
    const int lane = tid & 31;
    const int wid  = tid >> 5;

    const size_t base = (size_t)blockIdx.x * Tn + (size_t)tid * EPT;
    const float4* __restrict__ pe = reinterpret_cast<const float4*>(eps + base);
    const float4* __restrict__ pd = reinterpret_cast<const float4*>(dt  + base);

    // ---- 16 independent float4 streaming loads, batched up front ----
    float4 ev[NV], dv[NV];
    #pragma unroll
    for (int v = 0; v < NV; v++) ev[v] = __ldcs(pe + v);
    #pragma unroll
    for (int v = 0; v < NV; v++) dv[v] = __ldcs(pd + v);

    float ee[EPT], dd[EPT];
    #pragma unroll
    for (int v = 0; v < NV; v++) {
        ee[v*4+0] = ev[v].x; ee[v*4+1] = ev[v].y; ee[v*4+2] = ev[v].z; ee[v*4+3] = ev[v].w;
        dd[v*4+0] = dv[v].x; dd[v*4+1] = dv[v].y; dd[v*4+2] = dv[v].z; dd[v*4+3] = dv[v].w;
    }

    // ---- local affine fold; rewrite (ee,dd) -> (C, Pp) in place ----
    float P = 1.0f, Q = 0.0f;
    #pragma unroll
    for (int j = 0; j < EPT; j++) {
        float e = ee[j];
        float d = dd[j];
        dd[j] = P;                      // Pp_j
        ee[j] = fmaf(2.5f, e, -Q);      // C_j
        float ad = 0.5f * d;
        float A  = 1.0f - ad;
        Q = fmaf(A, Q, ad * e);
        P = P * A;
    }

    // ---- warp-inclusive affine scan (5 shuffle steps) ----
    #pragma unroll
    for (int off = 1; off < 32; off <<= 1) {
        float Pu = __shfl_up_sync(0xFFFFFFFFu, P, off);
        float Qu = __shfl_up_sync(0xFFFFFFFFu, Q, off);
        if (lane >= off) { Q = fmaf(P, Qu, Q); P *= Pu; }
    }
    // thread-exclusive prefix within warp
    float LPe = __shfl_up_sync(0xFFFFFFFFu, P, 1);
    float LQe = __shfl_up_sync(0xFFFFFFFFu, Q, 1);
    if (lane == 0) { LPe = 1.0f; LQe = 0.0f; }

    if (lane == 31) { sWP[wid] = P; sWQ[wid] = Q; }
    __syncthreads();

    // ---- redundant cross-warp scan in EVERY warp (no 2nd barrier) ----
    float p = (lane < NW) ? sWP[lane] : 1.0f;
    float q = (lane < NW) ? sWQ[lane] : 0.0f;
    #pragma unroll
    for (int off = 1; off < NW; off <<= 1) {
        float pu = __shfl_up_sync(0xFFFFFFFFu, p, off);
        float qu = __shfl_up_sync(0xFFFFFFFFu, q, off);
        if (lane >= off) { q = fmaf(p, qu, q); p *= pu; }
    }
    // block-start gamma = 0, so warp-start gamma = inclusive Q at wid-1.
    float gw = (wid == 0) ? 0.0f : __shfl_sync(0xFFFFFFFFu, q, wid - 1);
    float gt = fmaf(LPe, gw, LQe);      // thread-start gamma

    // ---- fixup (independent FMAs) + streaming float4 stores ----
    float4* __restrict__ po = reinterpret_cast<float4*>(out + base);
    #pragma unroll
    for (int v = 0; v < NV; v++) {
        float4 o;
        o.x = fmaf(-dd[v*4+0], gt, ee[v*4+0]);
        o.y = fmaf(-dd[v*4+1], gt, ee[v*4+1]);
        o.z = fmaf(-dd[v*4+2], gt, ee[v*4+2]);
        o.w = fmaf(-dd[v*4+3], gt, ee[v*4+3]);
        __stcs(po + v, o);
    }
}

extern "C" void kernel_launch(void* const* d_in, const int* in_sizes, int n_in,
                              void* d_out, int out_size) {
    const float* eps = (const float*)d_in[0];
    const float* dt  = (const float*)d_in[1];
    float* out = (float*)d_out;

    maxwell_row_kernel<<<Bn, TPB>>>(eps, dt, out);
}

// round 9
// speedup vs baseline: 1.1944x; 1.1944x over previous
#include <cuda_runtime.h>
#include <cstdint>

// Maxwell RNN: per-row linear recurrence, persistent CTAs with a
// double-buffered TMA (cp.async.bulk) smem pipeline.
//   gamma_t = (1 - 0.5*dt)*gamma_{t-1} + 0.5*dt*eps_t, gamma_{-1}=0
//   sig_t   = 2.5*eps_t - gamma_{t-1}
// One CTA = one SM, processes ~28 full rows; row k+2's TMA load streams
// while row k is computed from smem -> DRAM stays busy through compute.

constexpr int Bn   = 4096;
constexpr int Tn   = 8192;
constexpr int TPB  = 1024;
constexpr int EPT  = Tn / TPB;          // 8 elements per thread
constexpr int NW   = TPB / 32;          // 32 warps
constexpr int GRID = 148;
constexpr int ROWF = Tn;                // floats per row
constexpr int ROWB = Tn * 4;            // 32768 bytes per row
constexpr int SMEM_DYN = 4 * ROWB;      // 2 buffers x (eps row + dt row) = 128KB

__device__ __forceinline__ uint32_t smem_u32(const void* p) {
    uint32_t a;
    asm("{ .reg .u64 t; cvta.to.shared.u64 t, %1; cvt.u32.u64 %0, t; }"
        : "=r"(a) : "l"(p));
    return a;
}

__device__ __forceinline__ void mbar_init(uint32_t mbar, uint32_t count) {
    asm volatile("mbarrier.init.shared.b64 [%0], %1;" :: "r"(mbar), "r"(count) : "memory");
}
__device__ __forceinline__ void mbar_expect_tx(uint32_t mbar, uint32_t bytes) {
    asm volatile("mbarrier.arrive.expect_tx.shared.b64 _, [%0], %1;"
                 :: "r"(mbar), "r"(bytes) : "memory");
}
__device__ __forceinline__ void mbar_wait(uint32_t mbar, uint32_t phase) {
    asm volatile(
        "{\n\t.reg .pred P1;\n\t"
        "W%=:\n\t"
        "mbarrier.try_wait.parity.acquire.cta.shared::cta.b64 P1, [%0], %1, 0x989680;\n\t"
        "@P1 bra D%=;\n\t"
        "bra W%=;\n\t"
        "D%=:\n\t}"
        :: "r"(mbar), "r"(phase) : "memory");
}
__device__ __forceinline__ void tma_bulk_1d(uint32_t dst_smem, const void* src,
                                            uint32_t bytes, uint32_t mbar) {
    asm volatile(
        "cp.async.bulk.shared::cluster.global.mbarrier::complete_tx::bytes "
        "[%0], [%1], %2, [%3];"
        :: "r"(dst_smem), "l"(src), "r"(bytes), "r"(mbar) : "memory");
}

__global__ void __launch_bounds__(TPB)
maxwell_pipe_kernel(const float* __restrict__ eps, const float* __restrict__ dt,
                    float* __restrict__ out) {
    extern __shared__ float sm[];                  // [bufE0|bufD0|bufE1|bufD1]
    __shared__ uint64_t mbar_s[2];
    __shared__ float sWP[NW];
    __shared__ float sWQ[NW];

    const int tid  = threadIdx.x;
    const int lane = tid & 31;
    const int wid  = tid >> 5;
    const int bid  = blockIdx.x;
    const int cnt  = (Bn - bid + GRID - 1) / GRID; // rows for this CTA

    float* bufE[2] = { sm,            sm + 2 * ROWF };
    float* bufD[2] = { sm + ROWF,     sm + 3 * ROWF };
    const uint32_t mb[2] = { smem_u32(&mbar_s[0]), smem_u32(&mbar_s[1]) };

    if (tid == 0) { mbar_init(mb[0], 1); mbar_init(mb[1], 1); }
    __syncthreads();

    // ---- prologue: issue rows 0 and 1 ----
    if (tid == 0) {
        #pragma unroll
        for (int k = 0; k < 2; k++) {
            if (k < cnt) {
                size_t g = (size_t)(bid + k * GRID) * Tn;
                mbar_expect_tx(mb[k], 2 * ROWB);
                tma_bulk_1d(smem_u32(bufE[k]), eps + g, ROWB, mb[k]);
                tma_bulk_1d(smem_u32(bufD[k]), dt  + g, ROWB, mb[k]);
            }
        }
    }

    uint32_t ph0 = 0, ph1 = 0;

    for (int k = 0; k < cnt; k++) {
        const int b = k & 1;
        if (b == 0) { mbar_wait(mb[0], ph0); ph0 ^= 1u; }
        else        { mbar_wait(mb[1], ph1); ph1 ^= 1u; }

        // ---- read this thread's 8 eps + 8 dt from smem ----
        const float4* pE = reinterpret_cast<const float4*>(bufE[b] + tid * EPT);
        const float4* pD = reinterpret_cast<const float4*>(bufD[b] + tid * EPT);
        float4 e0 = pE[0], e1 = pE[1];
        float4 d0 = pD[0], d1 = pD[1];
        float ee[EPT] = { e0.x, e0.y, e0.z, e0.w, e1.x, e1.y, e1.z, e1.w };
        float dd[EPT] = { d0.x, d0.y, d0.z, d0.w, d1.x, d1.y, d1.z, d1.w };

        // ---- local affine fold; rewrite (ee,dd) -> (C, Pp) in place ----
        float P = 1.0f, Q = 0.0f;
        #pragma unroll
        for (int j = 0; j < EPT; j++) {
            float e = ee[j];
            float d = dd[j];
            dd[j] = P;                      // Pp_j
            ee[j] = fmaf(2.5f, e, -Q);      // C_j
            float ad = 0.5f * d;
            float A  = 1.0f - ad;
            Q = fmaf(A, Q, ad * e);
            P = P * A;
        }

        // ---- warp-inclusive affine scan ----
        #pragma unroll
        for (int off = 1; off < 32; off <<= 1) {
            float Pu = __shfl_up_sync(0xFFFFFFFFu, P, off);
            float Qu = __shfl_up_sync(0xFFFFFFFFu, Q, off);
            if (lane >= off) { Q = fmaf(P, Qu, Q); P *= Pu; }
        }
        float LPe = __shfl_up_sync(0xFFFFFFFFu, P, 1);
        float LQe = __shfl_up_sync(0xFFFFFFFFu, Q, 1);
        if (lane == 0) { LPe = 1.0f; LQe = 0.0f; }

        if (lane == 31) { sWP[wid] = P; sWQ[wid] = Q; }
        __syncthreads();

        // ---- redundant cross-warp scan in every warp (32 aggregates) ----
        float p = sWP[lane], q = sWQ[lane];
        #pragma unroll
        for (int off = 1; off < NW; off <<= 1) {
            float pu = __shfl_up_sync(0xFFFFFFFFu, p, off);
            float qu = __shfl_up_sync(0xFFFFFFFFu, q, off);
            if (lane >= off) { q = fmaf(p, qu, q); p *= pu; }
        }
        float gw = (wid == 0) ? 0.0f : __shfl_sync(0xFFFFFFFFu, q, wid - 1);
        float gt = fmaf(LPe, gw, LQe);      // thread-start gamma (row start = 0)

        // ---- fixup + coalesced stores ----
        const size_t gbase = (size_t)(bid + k * GRID) * Tn + (size_t)tid * EPT;
        float4 o0, o1;
        o0.x = fmaf(-dd[0], gt, ee[0]);
        o0.y = fmaf(-dd[1], gt, ee[1]);
        o0.z = fmaf(-dd[2], gt, ee[2]);
        o0.w = fmaf(-dd[3], gt, ee[3]);
        o1.x = fmaf(-dd[4], gt, ee[4]);
        o1.y = fmaf(-dd[5], gt, ee[5]);
        o1.z = fmaf(-dd[6], gt, ee[6]);
        o1.w = fmaf(-dd[7], gt, ee[7]);
        float4* po = reinterpret_cast<float4*>(out + gbase);
        po[0] = o0;
        po[1] = o1;

        __syncthreads();   // all threads done reading buffer b (and sWP/sWQ)

        // ---- refill buffer b with row k+2 ----
        if (tid == 0 && k + 2 < cnt) {
            size_t g = (size_t)(bid + (k + 2) * GRID) * Tn;
            mbar_expect_tx(mb[b], 2 * ROWB);
            tma_bulk_1d(smem_u32(bufE[b]), eps + g, ROWB, mb[b]);
            tma_bulk_1d(smem_u32(bufD[b]), dt  + g, ROWB, mb[b]);
        }
    }
}

extern "C" void kernel_launch(void* const* d_in, const int* in_sizes, int n_in,
                              void* d_out, int out_size) {
    const float* eps = (const float*)d_in[0];
    const float* dt  = (const float*)d_in[1];
    float* out = (float*)d_out;

    cudaFuncSetAttribute(maxwell_pipe_kernel,
                         cudaFuncAttributeMaxDynamicSharedMemorySize, SMEM_DYN);
    maxwell_pipe_kernel<<<GRID, TPB, SMEM_DYN>>>(eps, dt, out);
}

// round 10
// speedup vs baseline: 1.4763x; 1.2361x over previous
#include <cuda_runtime.h>

// Maxwell RNN: per-row linear recurrence. ONE WARP = ONE ROW, walked in 32
// chunks of 256 elements (8 per lane). Zero __syncthreads, zero smem, zero
// inter-warp coupling: warps free-run, so load/compute/store phases of the
// ~40 resident warps per SM interleave and DRAM demand stays steady.
//
//   gamma_t = (1 - 0.5*dt)*gamma_{t-1} + 0.5*dt*eps_t,  gamma_{-1} = 0
//   sig_t   = 2.5*eps_t - gamma_{t-1}
// Per chunk, sig is affine in the chunk-start state: sig_j = C_j - Pp_j*g.
// gamma carries across chunks via one broadcast: carry = P31*carry + Q31.

constexpr int Bn    = 4096;
constexpr int Tn    = 8192;
constexpr int TPB   = 256;
constexpr int WPB   = TPB / 32;        // 8 warps = 8 rows per block
constexpr int CHUNK = 256;             // elements per warp-chunk
constexpr int EPT   = 8;               // elements per lane per chunk
constexpr int NCH   = Tn / CHUNK;      // 32 chunks per row
constexpr int GRID  = Bn / WPB;        // 512 blocks

__global__ void __launch_bounds__(TPB)
maxwell_warp_kernel(const float* __restrict__ eps, const float* __restrict__ dt,
                    float* __restrict__ out) {
    const int lane = threadIdx.x & 31;
    const int wid  = threadIdx.x >> 5;

    const size_t rb = ((size_t)blockIdx.x * WPB + wid) * Tn;
    const float* pe = eps + rb;
    const float* pd = dt  + rb;
    float*       po = out + rb;
    const int toff = lane * EPT;

    // ---- prefetch chunk 0 ----
    float4 ce0 = *reinterpret_cast<const float4*>(pe + toff);
    float4 ce1 = *reinterpret_cast<const float4*>(pe + toff + 4);
    float4 cd0 = *reinterpret_cast<const float4*>(pd + toff);
    float4 cd1 = *reinterpret_cast<const float4*>(pd + toff + 4);

    float carry = 0.0f;                 // gamma entering current chunk

    #pragma unroll 2
    for (int c = 0; c < NCH; c++) {
        // ---- prefetch next chunk while current is processed ----
        float4 ne0, ne1, nd0, nd1;
        if (c + 1 < NCH) {
            const float* qe = pe + (c + 1) * CHUNK + toff;
            const float* qd = pd + (c + 1) * CHUNK + toff;
            ne0 = *reinterpret_cast<const float4*>(qe);
            ne1 = *reinterpret_cast<const float4*>(qe + 4);
            nd0 = *reinterpret_cast<const float4*>(qd);
            nd1 = *reinterpret_cast<const float4*>(qd + 4);
        }

        float ee[EPT] = { ce0.x, ce0.y, ce0.z, ce0.w, ce1.x, ce1.y, ce1.z, ce1.w };
        float dd[EPT] = { cd0.x, cd0.y, cd0.z, cd0.w, cd1.x, cd1.y, cd1.z, cd1.w };

        // ---- local affine fold; rewrite (ee,dd) -> (C, Pp) in place ----
        float P = 1.0f, Q = 0.0f;
        #pragma unroll
        for (int j = 0; j < EPT; j++) {
            float e = ee[j];
            float d = dd[j];
            dd[j] = P;                      // Pp_j
            ee[j] = fmaf(2.5f, e, -Q);      // C_j
            float ad = 0.5f * d;
            float A  = 1.0f - ad;
            Q = fmaf(A, Q, ad * e);
            P = P * A;
        }

        // ---- warp-inclusive affine scan (5 shuffle steps) ----
        #pragma unroll
        for (int off = 1; off < 32; off <<= 1) {
            float Pu = __shfl_up_sync(0xFFFFFFFFu, P, off);
            float Qu = __shfl_up_sync(0xFFFFFFFFu, Q, off);
            if (lane >= off) { Q = fmaf(P, Qu, Q); P *= Pu; }
        }
        // lane-exclusive prefix -> this lane's chunk-start gamma
        float LPe = __shfl_up_sync(0xFFFFFFFFu, P, 1);
        float LQe = __shfl_up_sync(0xFFFFFFFFu, Q, 1);
        if (lane == 0) { LPe = 1.0f; LQe = 0.0f; }
        float gt = fmaf(LPe, carry, LQe);

        // ---- carry gamma to next chunk (lane-31 inclusive aggregate) ----
        float P31 = __shfl_sync(0xFFFFFFFFu, P, 31);
        float Q31 = __shfl_sync(0xFFFFFFFFu, Q, 31);
        carry = fmaf(P31, carry, Q31);

        // ---- fixup (independent FMAs) + coalesced stores ----
        float4 o0, o1;
        o0.x = fmaf(-dd[0], gt, ee[0]);
        o0.y = fmaf(-dd[1], gt, ee[1]);
        o0.z = fmaf(-dd[2], gt, ee[2]);
        o0.w = fmaf(-dd[3], gt, ee[3]);
        o1.x = fmaf(-dd[4], gt, ee[4]);
        o1.y = fmaf(-dd[5], gt, ee[5]);
        o1.z = fmaf(-dd[6], gt, ee[6]);
        o1.w = fmaf(-dd[7], gt, ee[7]);
        float* w = po + c * CHUNK + toff;
        *reinterpret_cast<float4*>(w)     = o0;
        *reinterpret_cast<float4*>(w + 4) = o1;

        ce0 = ne0; ce1 = ne1; cd0 = nd0; cd1 = nd1;
    }
}

extern "C" void kernel_launch(void* const* d_in, const int* in_sizes, int n_in,
                              void* d_out, int out_size) {
    const float* eps = (const float*)d_in[0];
    const float* dt  = (const float*)d_in[1];
    float* out = (float*)d_out;

    maxwell_warp_kernel<<<GRID, TPB>>>(eps, dt, out);
}